// round 2
// baseline (speedup 1.0000x reference)
#include <cuda_runtime.h>

// Problem constants
#define BB 16
#define CC 12
#define MM 384
#define NN 384

#define TILE 32
#define HALO 8
#define SDIM (TILE + 2 * HALO)   // 48
#define NTHREADS 256
// 16 threads cover one 32-wide row (2 cols each); 256 threads -> 16 rows/pass
#define ROWS_PER_PASS (NTHREADS / (TILE / 2))   // 16

__global__ void wa_zero_kernel(float* __restrict__ out, int n) {
    int i = blockIdx.x * blockDim.x + threadIdx.x;
    if (i < n) out[i] = 0.0f;
}

__global__ __launch_bounds__(NTHREADS)
void wa_scatter_kernel(const float* __restrict__ x,
                       const float* __restrict__ u,
                       float* __restrict__ out)
{
    __shared__ float acc[SDIM * SDIM];

    const int tx0 = blockIdx.x * TILE;   // tile origin col
    const int ty0 = blockIdx.y * TILE;   // tile origin row
    const int b   = blockIdx.z;
    const int t   = threadIdx.x;

    #pragma unroll
    for (int k = t; k < SDIM * SDIM; k += NTHREADS) acc[k] = 0.0f;
    __syncthreads();

    float* __restrict__ outb = out + (size_t)b * MM * NN;

    const int lx  = (t & (TILE / 2 - 1)) * 2;  // 0,2,..,30 (pixel pair)
    const int ly0 = t >> 4;                    // 0..15
    const int j   = tx0 + lx;

    for (int c = 0; c < CC; ++c) {
        const size_t plane = ((size_t)b * CC + c) * (size_t)(MM * NN);
        const float* __restrict__ xp = x + plane;
        const float* __restrict__ up = u + plane * 2;

        #pragma unroll
        for (int ly = ly0; ly < TILE; ly += ROWS_PER_PASS) {
            const int i = ty0 + ly;
            const size_t idx = (size_t)i * NN + j;
            const float2 xv2 = *reinterpret_cast<const float2*>(xp + idx);
            const float4 uv4 = *reinterpret_cast<const float4*>(up + idx * 2);

            #pragma unroll
            for (int px = 0; px < 2; ++px) {
                const float xv = px ? xv2.y : xv2.x;
                const float ux = px ? uv4.z : uv4.x;
                const float uy = px ? uv4.w : uv4.y;
                const int   jp = j + px;

                const float tcx = (float)jp + ux;
                const float tcy = (float)i  + uy;
                const float fx = floorf(tcx);
                const float fy = floorf(tcy);
                const float wx = tcx - fx;
                const float wy = tcy - fy;
                const int x0 = (int)fx;
                const int y0 = (int)fy;

                const float omwx = 1.0f - wx;
                const float omwy = 1.0f - wy;
                const float w00 = omwy * omwx * xv;
                const float w01 = omwy * wx   * xv;
                const float w10 = wy   * omwx * xv;
                const float w11 = wy   * wx   * xv;

                const int sx = x0 - tx0 + HALO;
                const int sy = y0 - ty0 + HALO;

                if ((unsigned)sx <= (unsigned)(SDIM - 2) &&
                    (unsigned)sy <= (unsigned)(SDIM - 2)) {
                    float* p = acc + sy * SDIM + sx;
                    atomicAdd(p,            w00);
                    atomicAdd(p + 1,        w01);
                    atomicAdd(p + SDIM,     w10);
                    atomicAdd(p + SDIM + 1, w11);
                } else {
                    // Rare fallback (|u| > HALO-1): straight to global,
                    // dropping out-of-image corners (zero-pad convention).
                    #pragma unroll
                    for (int dy = 0; dy < 2; ++dy) {
                        #pragma unroll
                        for (int dx = 0; dx < 2; ++dx) {
                            const int yy = y0 + dy;
                            const int xx = x0 + dx;
                            if ((unsigned)yy < (unsigned)MM &&
                                (unsigned)xx < (unsigned)NN) {
                                const float w =
                                    (dy ? wy : omwy) * (dx ? wx : omwx) * xv;
                                atomicAdd(outb + (size_t)yy * NN + xx, w);
                            }
                        }
                    }
                }
            }
        }
    }

    __syncthreads();

    // Flush shared tile (incl. halo) to global via RED atomics; drop OOB.
    #pragma unroll
    for (int k = t; k < SDIM * SDIM; k += NTHREADS) {
        const float v = acc[k];
        if (v != 0.0f) {
            const int sy = k / SDIM;
            const int sx = k - sy * SDIM;
            const int gy = ty0 + sy - HALO;
            const int gx = tx0 + sx - HALO;
            if ((unsigned)gy < (unsigned)MM && (unsigned)gx < (unsigned)NN)
                atomicAdd(outb + (size_t)gy * NN + gx, v);
        }
    }
}

extern "C" void kernel_launch(void* const* d_in, const int* in_sizes, int n_in,
                              void* d_out, int out_size) {
    const float* x = (const float*)d_in[0];
    const float* u = (const float*)d_in[1];
    float* out = (float*)d_out;

    wa_zero_kernel<<<(out_size + 255) / 256, 256>>>(out, out_size);

    dim3 grid(NN / TILE, MM / TILE, BB);   // 12 x 12 x 16 = 2304 CTAs
    wa_scatter_kernel<<<grid, NTHREADS>>>(x, u, out);
}

// round 3
// speedup vs baseline: 1.4774x; 1.4774x over previous
#include <cuda_runtime.h>

// Problem constants
#define BB 16
#define CC 12
#define MM 384
#define NN 384

#define TILE 64
#define HALO 8
#define SROWS (TILE + 2 * HALO)   // 80 rows
#define SSTR  (SROWS + 1)         // 81 stride (odd -> bank-friendly)
#define NTHREADS 256
#define CGROUPS 2                 // coil split: 2 CTA groups x 6 coils
#define CPG (CC / CGROUPS)        // 6

__global__ void wa_zero_kernel(float* __restrict__ out, int n) {
    int i = blockIdx.x * blockDim.x + threadIdx.x;
    if (i < n) out[i] = 0.0f;
}

__device__ __forceinline__ void red_shared_f32(float* p, float v) {
    unsigned saddr = (unsigned)__cvta_generic_to_shared(p);
    asm volatile("red.shared.add.f32 [%0], %1;" :: "r"(saddr), "f"(v) : "memory");
}

__global__ __launch_bounds__(NTHREADS)
void wa_scatter_kernel(const float* __restrict__ x,
                       const float* __restrict__ u,
                       float* __restrict__ out)
{
    __shared__ float acc[SROWS * SSTR];

    const int tx0  = blockIdx.x * TILE;    // tile origin col
    const int ty0  = blockIdx.y * TILE;    // tile origin row
    const int b    = blockIdx.z & (BB - 1);
    const int cgrp = blockIdx.z >> 4;      // 0 or 1
    const int t    = threadIdx.x;

    #pragma unroll
    for (int k = t; k < SROWS * SSTR; k += NTHREADS) acc[k] = 0.0f;
    __syncthreads();

    float* __restrict__ outb = out + (size_t)b * MM * NN;

    const int lx  = t & (TILE - 1);        // 0..63, lane-contiguous cols
    const int ly0 = t >> 6;                // 0..3
    const int j   = tx0 + lx;

    for (int cc = 0; cc < CPG; ++cc) {
        const int c = cgrp * CPG + cc;
        const size_t plane = ((size_t)b * CC + c) * (size_t)(MM * NN);
        const float*  __restrict__ xp = x + plane;
        const float2* __restrict__ up = reinterpret_cast<const float2*>(u) + plane;

        #pragma unroll 4
        for (int ly = ly0; ly < TILE; ly += NTHREADS / TILE) {
            const int i = ty0 + ly;
            const size_t idx = (size_t)i * NN + j;
            const float  xv = xp[idx];
            const float2 uv = up[idx];     // uv.x = col disp, uv.y = row disp

            const float tcx = (float)j + uv.x;
            const float tcy = (float)i + uv.y;
            const float fx = floorf(tcx);
            const float fy = floorf(tcy);
            const float wx = tcx - fx;
            const float wy = tcy - fy;
            const int x0 = (int)fx;
            const int y0 = (int)fy;

            const float omwx = 1.0f - wx;
            const float omwy = 1.0f - wy;
            const float w00 = omwy * omwx * xv;
            const float w01 = omwy * wx   * xv;
            const float w10 = wy   * omwx * xv;
            const float w11 = wy   * wx   * xv;

            const int sx = x0 - tx0 + HALO;
            const int sy = y0 - ty0 + HALO;

            if ((unsigned)sx <= (unsigned)(SROWS - 2) &&
                (unsigned)sy <= (unsigned)(SROWS - 2)) {
                float* p = acc + sy * SSTR + sx;
                red_shared_f32(p,            w00);
                red_shared_f32(p + 1,        w01);
                red_shared_f32(p + SSTR,     w10);
                red_shared_f32(p + SSTR + 1, w11);
            } else {
                // Rare fallback (|u| > HALO-1): straight to global,
                // dropping out-of-image corners (zero-pad convention).
                #pragma unroll
                for (int dy = 0; dy < 2; ++dy) {
                    #pragma unroll
                    for (int dx = 0; dx < 2; ++dx) {
                        const int yy = y0 + dy;
                        const int xx = x0 + dx;
                        if ((unsigned)yy < (unsigned)MM &&
                            (unsigned)xx < (unsigned)NN) {
                            const float w =
                                (dy ? wy : omwy) * (dx ? wx : omwx) * xv;
                            atomicAdd(outb + (size_t)yy * NN + xx, w);
                        }
                    }
                }
            }
        }
    }

    __syncthreads();

    // Flush shared tile (incl. halo) to global via RED atomics; drop OOB.
    #pragma unroll
    for (int k = t; k < SROWS * SSTR; k += NTHREADS) {
        const int sy = k / SSTR;
        const int sx = k - sy * SSTR;
        if (sx >= SROWS) continue;         // stride padding column
        const float v = acc[k];
        if (v != 0.0f) {
            const int gy = ty0 + sy - HALO;
            const int gx = tx0 + sx - HALO;
            if ((unsigned)gy < (unsigned)MM && (unsigned)gx < (unsigned)NN)
                atomicAdd(outb + (size_t)gy * NN + gx, v);
        }
    }
}

extern "C" void kernel_launch(void* const* d_in, const int* in_sizes, int n_in,
                              void* d_out, int out_size) {
    const float* x = (const float*)d_in[0];
    const float* u = (const float*)d_in[1];
    float* out = (float*)d_out;

    wa_zero_kernel<<<(out_size + 255) / 256, 256>>>(out, out_size);

    dim3 grid(NN / TILE, MM / TILE, BB * CGROUPS);  // 6 x 6 x 32 = 1152 CTAs
    wa_scatter_kernel<<<grid, NTHREADS>>>(x, u, out);
}

// round 4
// speedup vs baseline: 1.6895x; 1.1436x over previous
#include <cuda_runtime.h>

// Problem constants
#define BB 16
#define CC 12
#define MM 384
#define NN 384

#define TILE 64
#define HALO 4
#define SROWS (TILE + 2 * HALO)   // 72 rows, 72 live cols
#define SSTR  96                  // floats; 384B = 3*128B -> bank = sx mod 32
#define NTHREADS 256
#define CGROUPS 2                 // coil split: 2 CTA groups x 6 coils
#define CPG (CC / CGROUPS)        // 6

__device__ __forceinline__ void red_shared_f32(float* p, float v) {
    unsigned saddr = (unsigned)__cvta_generic_to_shared(p);
    asm volatile("red.shared.add.f32 [%0], %1;" :: "r"(saddr), "f"(v) : "memory");
}

__global__ __launch_bounds__(NTHREADS)
void wa_scatter_kernel(const float* __restrict__ x,
                       const float* __restrict__ u,
                       float* __restrict__ out)
{
    __shared__ __align__(16) float acc[SROWS * SSTR];

    const int tx0  = blockIdx.x * TILE;    // tile origin col
    const int ty0  = blockIdx.y * TILE;    // tile origin row
    const int b    = blockIdx.z & (BB - 1);
    const int cgrp = blockIdx.z >> 4;      // 0 or 1
    const int t    = threadIdx.x;

    // zero accumulator (vectorized)
    {
        float4* a4 = reinterpret_cast<float4*>(acc);
        const float4 z4 = make_float4(0.f, 0.f, 0.f, 0.f);
        #pragma unroll
        for (int k = t; k < SROWS * SSTR / 4; k += NTHREADS) a4[k] = z4;
    }
    __syncthreads();

    float* __restrict__ outb = out + (size_t)b * MM * NN;

    const int lx  = t & (TILE - 1);        // 0..63, lane-contiguous cols
    const int ly0 = t >> 6;                // 0..3
    const int j   = tx0 + lx;

    for (int cc = 0; cc < CPG; ++cc) {
        const int c = cgrp * CPG + cc;
        const size_t plane = ((size_t)b * CC + c) * (size_t)(MM * NN);
        const float*  __restrict__ xp = x + plane;
        const float2* __restrict__ up = reinterpret_cast<const float2*>(u) + plane;

        #pragma unroll 4
        for (int ly = ly0; ly < TILE; ly += NTHREADS / TILE) {
            const int i = ty0 + ly;
            const size_t idx = (size_t)i * NN + j;
            const float  xv = xp[idx];
            const float2 uv = up[idx];     // uv.x = col disp, uv.y = row disp

            const float tcx = (float)j + uv.x;
            const float tcy = (float)i + uv.y;
            const float fx = floorf(tcx);
            const float fy = floorf(tcy);
            const float wx = tcx - fx;
            const float wy = tcy - fy;
            const int x0 = (int)fx;
            const int y0 = (int)fy;

            const float omwx = 1.0f - wx;
            const float omwy = 1.0f - wy;
            const float w00 = omwy * omwx * xv;
            const float w01 = omwy * wx   * xv;
            const float w10 = wy   * omwx * xv;
            const float w11 = wy   * wx   * xv;

            const int sx = x0 - tx0 + HALO;
            const int sy = y0 - ty0 + HALO;

            if ((unsigned)sx <= (unsigned)(SROWS - 2) &&
                (unsigned)sy <= (unsigned)(SROWS - 2)) {
                float* p = acc + sy * SSTR + sx;
                red_shared_f32(p,            w00);
                red_shared_f32(p + 1,        w01);
                red_shared_f32(p + SSTR,     w10);
                red_shared_f32(p + SSTR + 1, w11);
            } else {
                // Rare fallback (|u| beyond halo): straight to global,
                // dropping out-of-image corners (zero-pad convention).
                #pragma unroll
                for (int dy = 0; dy < 2; ++dy) {
                    #pragma unroll
                    for (int dx = 0; dx < 2; ++dx) {
                        const int yy = y0 + dy;
                        const int xx = x0 + dx;
                        if ((unsigned)yy < (unsigned)MM &&
                            (unsigned)xx < (unsigned)NN) {
                            const float w =
                                (dy ? wy : omwy) * (dx ? wx : omwx) * xv;
                            atomicAdd(outb + (size_t)yy * NN + xx, w);
                        }
                    }
                }
            }
        }
    }

    __syncthreads();

    // Flush shared tile (incl. halo) to global with vector REDs.
    // Row of 72 live cells = 18 float4 groups; OOB margins are whole groups
    // (HALO=4 and tx0 % 4 == 0), so groups are all-in or all-out.
    {
        const int GROUPS_PER_ROW = SROWS / 4;           // 18
        const int NGROUPS = SROWS * GROUPS_PER_ROW;     // 1296
        #pragma unroll
        for (int g = t; g < NGROUPS; g += NTHREADS) {
            const int sy = g / GROUPS_PER_ROW;
            const int sx = (g - sy * GROUPS_PER_ROW) * 4;
            const int gy = ty0 + sy - HALO;
            const int gx = tx0 + sx - HALO;
            if ((unsigned)gy < (unsigned)MM && (unsigned)gx < (unsigned)NN) {
                const float4 v =
                    *reinterpret_cast<const float4*>(acc + sy * SSTR + sx);
                atomicAdd(reinterpret_cast<float4*>(
                              outb + (size_t)gy * NN + gx), v);
            }
        }
    }
}

extern "C" void kernel_launch(void* const* d_in, const int* in_sizes, int n_in,
                              void* d_out, int out_size) {
    const float* x = (const float*)d_in[0];
    const float* u = (const float*)d_in[1];
    float* out = (float*)d_out;

    // out is poisoned; zero it (memset node, graph-capturable).
    cudaMemsetAsync(out, 0, (size_t)out_size * sizeof(float));

    dim3 grid(NN / TILE, MM / TILE, BB * CGROUPS);  // 6 x 6 x 32 = 1152 CTAs
    wa_scatter_kernel<<<grid, NTHREADS>>>(x, u, out);
}